// round 3
// baseline (speedup 1.0000x reference)
#include <cuda_runtime.h>

#define PH 7
#define PW 7
#define NN 4
#define CC 128
#define HH 50
#define WW 50
#define SCALE 0.0625f

// channel-last scratch: [N][H][W][C], 4*50*50*128 floats = 5.12 MB
__device__ float g_featT[NN * HH * WW * CC];

__global__ void transpose_kernel(const float* __restrict__ feat) {
    // one block per (b, h) plane: transpose [C,W] -> [W,C]
    int bh = blockIdx.x;
    int b = bh / HH;
    int h = bh % HH;
    __shared__ float tile[CC * WW];  // 25.6 KB

    const float* src = feat + ((long)b * CC) * (HH * WW) + h * WW;
    for (int i = threadIdx.x; i < CC * WW; i += blockDim.x) {
        int c = i / WW;
        int w = i % WW;
        tile[i] = src[(long)c * (HH * WW) + w];
    }
    __syncthreads();
    float* dst = g_featT + ((long)(b * HH + h) * WW) * CC;
    for (int i = threadIdx.x; i < CC * WW; i += blockDim.x) {
        int w = i / CC;
        int c = i % CC;
        dst[i] = tile[c * WW + w];
    }
}

__global__ void roipool_kernel(const float* __restrict__ rois,
                               float* __restrict__ out) {
    // one warp per (k, ph, cgroup); lane = channel within cgroup
    int gwarp = blockIdx.x * (blockDim.x >> 5) + (threadIdx.x >> 5);
    int lane = threadIdx.x & 31;

    int cg = gwarp & 3;            // 4 channel groups of 32
    int ph = (gwarp >> 2) % PH;
    int k  = gwarp / (4 * PH);
    int c  = cg * 32 + lane;

    const float* r = rois + k * 5;
    int b  = (int)__ldg(r + 0);
    int x1 = (int)rintf(__ldg(r + 1) * SCALE);
    int y1 = (int)rintf(__ldg(r + 2) * SCALE);
    int x2 = (int)rintf(__ldg(r + 3) * SCALE);
    int y2 = (int)rintf(__ldg(r + 4) * SCALE);

    float roi_w = (float)max(x2 - x1 + 1, 1);
    float roi_h = (float)max(y2 - y1 + 1, 1);
    float bw = roi_w * (1.0f / PW);
    float bh = roi_h * (1.0f / PH);

    int hs = min(max((int)floorf((float)ph * bh) + y1, 0), HH);
    int he = min(max((int)ceilf((float)(ph + 1) * bh) + y1, 0), HH);

    const float* fT = g_featT + ((long)b * HH * WW) * CC + c;
    float* o = out + ((long)(k * CC + c) * PH + ph) * PW;

    #pragma unroll
    for (int pw = 0; pw < PW; pw++) {
        int ws = min(max((int)floorf((float)pw * bw) + x1, 0), WW);
        int we = min(max((int)ceilf((float)(pw + 1) * bw) + x1, 0), WW);
        bool empty = (he <= hs) || (we <= ws);
        float m = -3.402823466e+38f;
        for (int h = hs; h < he; h++) {
            const float* rowp = fT + (long)(h * WW) * CC;
            for (int w = ws; w < we; w++) {
                m = fmaxf(m, __ldg(rowp + (long)w * CC));
            }
        }
        o[pw] = empty ? 0.0f : m;
    }
}

extern "C" void kernel_launch(void* const* d_in, const int* in_sizes, int n_in,
                              void* d_out, int out_size) {
    const float* feat = (const float*)d_in[0];
    const float* rois = (const float*)d_in[1];
    float* out = (float*)d_out;

    transpose_kernel<<<NN * HH, 256>>>(feat);

    // warps needed: K * PH * 4 = 256 * 7 * 4 = 7168; 8 warps per block
    int K = in_sizes[1] / 5;
    int warps = K * PH * 4;
    int blocks = warps / 8;
    roipool_kernel<<<blocks, 256>>>(rois, out);
}

// round 4
// speedup vs baseline: 2.0938x; 2.0938x over previous
#include <cuda_runtime.h>
#include <cfloat>

#define PH 7
#define PW 7
#define NN 4
#define CC 128
#define HH 50
#define WW 50
#define SCALE 0.0625f

// channel-last scratch: [N][H][W][C], 4*50*50*128 floats = 5.12 MB
__device__ float g_featT[NN * HH * WW * CC];

// transpose [C,W] -> [W,C] per (b,h,c-half)
__global__ void transpose_kernel(const float* __restrict__ feat) {
    int blk = blockIdx.x;
    int b    = blk / (HH * 2);
    int rest = blk % (HH * 2);
    int h    = rest >> 1;
    int c0   = (rest & 1) * 64;

    __shared__ float tile[64 * WW];  // 12.8 KB

    const float* src = feat + ((long)b * CC + c0) * (HH * WW) + h * WW;
    for (int i = threadIdx.x; i < 64 * WW; i += blockDim.x) {
        int c = i / WW;
        int w = i % WW;
        tile[i] = src[(long)c * (HH * WW) + w];
    }
    __syncthreads();
    float* dst = g_featT + ((long)(b * HH + h) * WW) * CC + c0;
    for (int i = threadIdx.x; i < 64 * WW; i += blockDim.x) {
        int w = i >> 6;       // i / 64
        int c = i & 63;       // i % 64
        dst[(long)w * CC + c] = tile[c * WW + w];
    }
}

// one block per (k, ph); 7 warps, warp = pw bin; lane = 4 channels (float4)
__global__ void roipool_kernel(const float* __restrict__ rois,
                               float* __restrict__ out) {
    int k  = blockIdx.x / PH;
    int ph = blockIdx.x % PH;
    int warp = threadIdx.x >> 5;   // = pw
    int lane = threadIdx.x & 31;

    __shared__ float so[CC * (PW + 1)];  // [c][pw] padded, 4 KB

    const float* r = rois + k * 5;
    int b  = (int)__ldg(r + 0);
    int x1 = (int)rintf(__ldg(r + 1) * SCALE);
    int y1 = (int)rintf(__ldg(r + 2) * SCALE);
    int x2 = (int)rintf(__ldg(r + 3) * SCALE);
    int y2 = (int)rintf(__ldg(r + 4) * SCALE);

    float roi_w = (float)max(x2 - x1 + 1, 1);
    float roi_h = (float)max(y2 - y1 + 1, 1);
    float bw = roi_w * (1.0f / PW);
    float bh = roi_h * (1.0f / PH);

    int hs = min(max((int)floorf((float)ph * bh) + y1, 0), HH);
    int he = min(max((int)ceilf((float)(ph + 1) * bh) + y1, 0), HH);
    int pw = warp;
    int ws = min(max((int)floorf((float)pw * bw) + x1, 0), WW);
    int we = min(max((int)ceilf((float)(pw + 1) * bw) + x1, 0), WW);
    bool empty = (he <= hs) || (we <= ws);

    const float4* fT4 = reinterpret_cast<const float4*>(
        g_featT + ((long)b * HH * WW) * CC) + lane;   // lane*4 channels

    float4 m = make_float4(-FLT_MAX, -FLT_MAX, -FLT_MAX, -FLT_MAX);
    for (int h = hs; h < he; h++) {
        const float4* rowp = fT4 + (long)(h * WW) * (CC / 4);
        for (int w = ws; w < we; w++) {
            float4 v = __ldg(rowp + (long)w * (CC / 4));
            m.x = fmaxf(m.x, v.x);
            m.y = fmaxf(m.y, v.y);
            m.z = fmaxf(m.z, v.z);
            m.w = fmaxf(m.w, v.w);
        }
    }
    if (empty) m = make_float4(0.f, 0.f, 0.f, 0.f);

    int c = lane * 4;
    so[(c + 0) * (PW + 1) + pw] = m.x;
    so[(c + 1) * (PW + 1) + pw] = m.y;
    so[(c + 2) * (PW + 1) + pw] = m.z;
    so[(c + 3) * (PW + 1) + pw] = m.w;
    __syncthreads();

    // write 896 floats: out[k*6272 + c*49 + ph*7 + pw]
    float* ok = out + (long)k * (CC * PH * PW) + ph * PW;
    for (int e = threadIdx.x; e < CC * PW; e += blockDim.x) {
        int cc = e / PW;
        int ppw = e % PW;
        ok[cc * (PH * PW) + ppw] = so[cc * (PW + 1) + ppw];
    }
}

extern "C" void kernel_launch(void* const* d_in, const int* in_sizes, int n_in,
                              void* d_out, int out_size) {
    const float* feat = (const float*)d_in[0];
    const float* rois = (const float*)d_in[1];
    float* out = (float*)d_out;

    transpose_kernel<<<NN * HH * 2, 256>>>(feat);

    int K = in_sizes[1] / 5;   // 256
    roipool_kernel<<<K * PH, PW * 32>>>(rois, out);
}

// round 5
// speedup vs baseline: 2.2583x; 1.0785x over previous
#include <cuda_runtime.h>
#include <cfloat>

#define PH 7
#define PW 7
#define NN 4
#define CC 128
#define HH 50
#define WW 50
#define SCALE 0.0625f

// channel-last scratch: [N][H][W][C], 5.12 MB
__device__ float g_featT[NN * HH * WW * CC];

// transpose [C,W] -> [W,C] per (b,h,c-half)
__global__ void transpose_kernel(const float* __restrict__ feat) {
    int blk = blockIdx.x;
    int b    = blk / (HH * 2);
    int rest = blk % (HH * 2);
    int h    = rest >> 1;
    int c0   = (rest & 1) * 64;

    __shared__ float tile[64 * WW];  // 12.8 KB

    const float* src = feat + ((long)b * CC + c0) * (HH * WW) + h * WW;
    for (int i = threadIdx.x; i < 64 * WW; i += blockDim.x) {
        int c = i / WW;
        int w = i % WW;
        tile[i] = src[(long)c * (HH * WW) + w];
    }
    __syncthreads();
    float* dst = g_featT + ((long)(b * HH + h) * WW) * CC + c0;
    for (int i = threadIdx.x; i < 64 * WW; i += blockDim.x) {
        int w = i >> 6;
        int c = i & 63;
        dst[(long)w * CC + c] = tile[c * WW + w];
    }
}

// one block per (k, ph); 14 warps: warp = (chalf, pw); lane = 2 channels (float2)
__global__ __launch_bounds__(448) void roipool_kernel(const float* __restrict__ rois,
                                                      float* __restrict__ out) {
    int k  = blockIdx.x / PH;
    int ph = blockIdx.x % PH;
    int wid  = threadIdx.x >> 5;   // 0..13
    int lane = threadIdx.x & 31;
    int pw    = wid % PW;
    int chalf = wid / PW;          // 0 or 1

    __shared__ float so[PW * CC];  // [pw][c], 3.5 KB

    const float* r = rois + k * 5;
    int b  = (int)__ldg(r + 0);
    int x1 = (int)rintf(__ldg(r + 1) * SCALE);
    int y1 = (int)rintf(__ldg(r + 2) * SCALE);
    int x2 = (int)rintf(__ldg(r + 3) * SCALE);
    int y2 = (int)rintf(__ldg(r + 4) * SCALE);

    float roi_w = (float)max(x2 - x1 + 1, 1);
    float roi_h = (float)max(y2 - y1 + 1, 1);
    float bw = roi_w * (1.0f / PW);
    float bh = roi_h * (1.0f / PH);

    int hs = min(max((int)floorf((float)ph * bh) + y1, 0), HH);
    int he = min(max((int)ceilf((float)(ph + 1) * bh) + y1, 0), HH);
    int ws = min(max((int)floorf((float)pw * bw) + x1, 0), WW);
    int we = min(max((int)ceilf((float)(pw + 1) * bw) + x1, 0), WW);
    bool empty = (he <= hs) || (we <= ws);

    // lane covers channels c = chalf*64 + lane*2, c+1
    const float2* fT2 = reinterpret_cast<const float2*>(
        g_featT + ((long)b * HH * WW) * CC) + (chalf * 32 + lane);

    float m0 = -FLT_MAX, m1 = -FLT_MAX;
    for (int h = hs; h < he; h++) {
        const float2* rowp = fT2 + (long)(h * WW) * (CC / 2);
        #pragma unroll 4
        for (int w = ws; w < we; w++) {
            float2 v = __ldg(rowp + (long)w * (CC / 2));
            m0 = fmaxf(m0, v.x);
            m1 = fmaxf(m1, v.y);
        }
    }
    if (empty) { m0 = 0.f; m1 = 0.f; }

    // contiguous float2 STS, conflict-free
    reinterpret_cast<float2*>(so + pw * CC)[chalf * 32 + lane] =
        make_float2(m0, m1);
    __syncthreads();

    // write 896 floats: out[k*6272 + c*49 + ph*7 + pw]
    float* ok = out + (long)k * (CC * PH * PW) + ph * PW;
    for (int e = threadIdx.x; e < CC * PW; e += blockDim.x) {
        int cc  = e / PW;
        int ppw = e % PW;
        ok[cc * (PH * PW) + ppw] = so[ppw * CC + cc];
    }
}

extern "C" void kernel_launch(void* const* d_in, const int* in_sizes, int n_in,
                              void* d_out, int out_size) {
    const float* feat = (const float*)d_in[0];
    const float* rois = (const float*)d_in[1];
    float* out = (float*)d_out;

    transpose_kernel<<<NN * HH * 2, 256>>>(feat);

    int K = in_sizes[1] / 5;   // 256
    roipool_kernel<<<K * PH, 448>>>(rois, out);
}